// round 9
// baseline (speedup 1.0000x reference)
#include <cuda_runtime.h>
#include <cstdint>

#define N_NODES 100000
#define D 64
#define VEC_PER_ROW (D / 4)      // 16 float4 per node row
#define N_EDGES 1600000
#define BUCKET_CAP 64            // Poisson(16): P(deg>=64) ~ 1e-18 per node

// Static scratch (allocation-free rule). g_counts is zero at module load and
// re-zeroed by aggregate_kernel at the end of every launch sequence.
__device__ int g_counts[N_NODES];               // in-degree (excl. self-loop)
__device__ int g_bucket[N_NODES * BUCKET_CAP];  // src ids, padded per dst

// ---------------------------------------------------------------- fill
// One kernel replaces count+scan+fill: atomically claim a slot in the
// destination's fixed-capacity bucket.
__global__ void fill_kernel(const int* __restrict__ ei) {
    int e = blockIdx.x * blockDim.x + threadIdx.x;
    if (e < N_EDGES) {
        int src = ei[e];
        int dst = ei[N_EDGES + e];
        int pos = atomicAdd(&g_counts[dst], 1);
        if (pos < BUCKET_CAP) g_bucket[dst * BUCKET_CAP + pos] = src;
    }
}

// ---------------------------------------------------------------- aggregate
// One warp per destination node. Lane c<16 handles float4 chunk c of the real
// row; lane c>=16 handles chunk c-16 of the imag row. Accumulator starts with
// the node's own row (self-loop); final scale 1/(deg+1) gives the mean.
// Neighbor indices are preloaded (2 coalesced slots per lane) and broadcast
// via shuffle, so the gather loop contains only the float4 gathers.
// Lane 0 re-zeroes g_counts[n] after use so the next graph replay starts clean.
__global__ void aggregate_kernel(const float* __restrict__ Zr,
                                 const float* __restrict__ Zi,
                                 float* __restrict__ out) {
    int warp_id = (blockIdx.x * blockDim.x + threadIdx.x) >> 5;
    int lane = threadIdx.x & 31;
    if (warp_id >= N_NODES) return;
    int n = warp_id;

    const float4* Zr4 = (const float4*)Zr;
    const float4* Zi4 = (const float4*)Zi;

    bool is_real = lane < 16;
    int chunk = is_real ? lane : lane - 16;

    // self-loop init
    float4 acc = is_real ? Zr4[(size_t)n * VEC_PER_ROW + chunk]
                         : Zi4[(size_t)n * VEC_PER_ROW + chunk];

    int count = g_counts[n];
    if (lane == 0) g_counts[n] = 0;          // reset for next graph replay
    int deg = (count < BUCKET_CAP) ? count : BUCKET_CAP;

    // Preload up to 64 neighbor ids: lane j holds slots j and j+32.
    const int* bkt = g_bucket + (size_t)n * BUCKET_CAP;
    int idx0 = (lane < deg) ? bkt[lane] : 0;
    int idx1 = (lane + 32 < deg) ? bkt[lane + 32] : 0;

    for (int j = 0; j < deg; j++) {
        int s = (j < 32) ? __shfl_sync(0xFFFFFFFFu, idx0, j)
                         : __shfl_sync(0xFFFFFFFFu, idx1, j - 32);
        float4 v = is_real ? Zr4[(size_t)s * VEC_PER_ROW + chunk]
                           : Zi4[(size_t)s * VEC_PER_ROW + chunk];
        acc.x += v.x; acc.y += v.y; acc.z += v.z; acc.w += v.w;
    }

    float inv = 1.0f / (float)(count + 1);
    acc.x *= inv; acc.y *= inv; acc.z *= inv; acc.w *= inv;

    float4* o = is_real ? (float4*)out : (float4*)(out + (size_t)N_NODES * D);
    o[(size_t)n * VEC_PER_ROW + chunk] = acc;
}

// ---------------------------------------------------------------- launch
extern "C" void kernel_launch(void* const* d_in, const int* in_sizes, int n_in,
                              void* d_out, int out_size) {
    const float* Zr = (const float*)d_in[0];
    const float* Zi = (const float*)d_in[1];
    const int* ei = (const int*)d_in[2];
    float* out = (float*)d_out;

    {
        int threads = 256;
        int blocks = (N_EDGES + threads - 1) / threads;
        fill_kernel<<<blocks, threads>>>(ei);
    }
    {
        // one warp per node: 100000 warps, 8 warps (256 threads) per block
        int threads = 256;
        int blocks = (N_NODES * 32 + threads - 1) / threads;  // 12500
        aggregate_kernel<<<blocks, threads>>>(Zr, Zi, out);
    }
}